// round 11
// baseline (speedup 1.0000x reference)
#include <cuda_runtime.h>
#include <cuda_bf16.h>
#include <cstdint>

// ---------------------------------------------------------------------------
// Mobile2Former cross-attention, single-pass streaming softmax (scores bounded
// |s| < ~2; softmax shift-invariant so no max subtraction needed).
//
//   x : (64, 96, 112, 112) fp32 -> xf (b, n=12544, c=96), K = V = xf
//   q = SCALE * (z @ Wq + bq); p = exp(q.xf); out = (p@xf)/sum(p)
//   y = z + out @ Wo + bo
//
// Launch order: marker, qproj, marker, attn, combine, proj
//   (ncu captures absolute launch index 3 -> attn)
//
// attn (R11): wave-exact partition. Grid = 888 = 2 x (148 SMs x occ 3).
// Work = 6272 (b, pair) units; CTAs 0..55 take 8 pairs, 56..887 take 7.
// A CTA crossing a batch boundary flushes its partials for the old batch to
// slot (2*cta+seg) with a batch tag, reloads Q, continues. Compute bodies
// (pair Phase A, Phase B, packed f32x2) identical to R10.
// ---------------------------------------------------------------------------

#define BATCH   64
#define CHN     96
#define HWN     12544
#define NHM     24
#define TN      64
#define TNP     68             // padded row stride (floats); 272B, 16B-aligned
#define PAIRS_PER_B 98         // 12544 / 128
#define PAIRS_TOTAL (BATCH * PAIRS_PER_B)   // 6272
#define GRID2   888            // 2 x 444 slots exactly
#define LONGC   56             // 6272 - 888*7
#define NSLOTS  (2 * GRID2)    // per-(CTA, segment) partial slots
#define THREADS2 128
#define XS_FLOATS (CHN * TNP)                 // 6528 per buffer
#define PS_FLOATS (NHM * TNP)                 // 1632 per tile
#define SMEM2_FLOATS (2*XS_FLOATS + 2*PS_FLOATS + CHN*NHM + 48)  // 18672
#define SMEM2_BYTES  (SMEM2_FLOATS * 4)       // 74688 B (3 CTAs/SM)
#define SCALE_F 0.10206207261596575f          // 96^-0.5

__device__ float g_Qp[2][BATCH * NHM * CHN];        // K-split q partials
__device__ float g_accP[NSLOTS * NHM * CHN];        // per-slot partial numerators
__device__ float g_LP[NSLOTS * NHM];                // per-slot partial denominators
__device__ int   g_slotb[NSLOTS];                   // slot -> batch tag (-1 unused)
__device__ float g_O[BATCH * 6 * 384];              // attn out [b][m][h*96+c]

// ---- packed f32x2 helpers ----
__device__ __forceinline__ unsigned long long pack2(float a, float b) {
    unsigned long long r;
    asm("mov.b64 %0, {%1, %2};" : "=l"(r) : "f"(a), "f"(b));
    return r;
}
__device__ __forceinline__ void unpack2(unsigned long long v, float& a, float& b) {
    asm("mov.b64 {%0, %1}, %2;" : "=f"(a), "=f"(b) : "l"(v));
}
__device__ __forceinline__ void fma2(unsigned long long& d,
                                     unsigned long long a, unsigned long long b) {
    asm("fma.rn.f32x2 %0, %1, %2, %0;" : "+l"(d) : "l"(a), "l"(b));
}
__device__ __forceinline__ void add2(unsigned long long& d, unsigned long long a) {
    asm("add.rn.f32x2 %0, %1, %0;" : "+l"(d) : "l"(a));
}
__device__ __forceinline__ void cp_async16(uint32_t dst, const float* src) {
    asm volatile("cp.async.cg.shared.global [%0], [%1], 16;" :: "r"(dst), "l"(src));
}

// pair index -> owning CTA (must mirror the start computation in attn)
__device__ __forceinline__ int cta_of_pair(int p) {
    return (p < LONGC * 8) ? (p >> 3) : (LONGC + (p - LONGC * 8) / 7);
}

__global__ void prof_marker() {}

// ---------------------------------------------------------------------------
// Kernel 1: Q projection, grid (BATCH, 2): grid.y = K-half (d in [96h,96h+96)).
// ---------------------------------------------------------------------------
__global__ __launch_bounds__(384)
void qproj_kernel(const float* __restrict__ z,
                  const float* __restrict__ Wq,
                  const float* __restrict__ bq) {
    __shared__ float zs[6 * 192];
    const int b = blockIdx.x;
    const int half = blockIdx.y;
    const int j = threadIdx.x;          // output column 0..383
    for (int i = j; i < 6 * 192; i += 384) zs[i] = z[b * 6 * 192 + i];
    __syncthreads();

    const int d0 = 96 * half;
    float acc[6] = {0.f, 0.f, 0.f, 0.f, 0.f, 0.f};
    #pragma unroll 16
    for (int dd = 0; dd < 96; dd++) {
        const float w = Wq[(d0 + dd) * 384 + j];   // coalesced across block
        #pragma unroll
        for (int m = 0; m < 6; m++) acc[m] += zs[m * 192 + d0 + dd] * w;
    }
    const int h = j / CHN, c = j % CHN;
    const float bias = (half == 0) ? bq[j] : 0.f;
    #pragma unroll
    for (int m = 0; m < 6; m++)
        g_Qp[half][(size_t)b * (NHM * CHN) + (h * 6 + m) * CHN + c] =
            (acc[m] + bias) * SCALE_F;
}

// ---------------------------------------------------------------------------
// Kernel 2: streaming attention, wave-exact (b, pair) partition.
// ---------------------------------------------------------------------------
__global__ __launch_bounds__(THREADS2, 3)
void attn_kernel(const float* __restrict__ x) {
    extern __shared__ float sm[];
    float* Xs0  = sm;                          // [2][96][68]
    float* Ps0  = sm + 2 * XS_FLOATS;          // [24][68] tile A (also flush staging)
    float* Ps1  = Ps0 + PS_FLOATS;             // [24][68] tile B
    float* Qs   = Ps1 + PS_FLOATS;             // [96][24] transposed
    float* Lred = Qs + CHN * NHM;              // [4][12]

    const int t    = threadIdx.x;
    const int cta  = blockIdx.x;
    const int lane = t & 31;
    const int wq   = t >> 5;
    const int g    = t >> 6;                   // phase-A hm-half
    const int ng   = t & 63;                   // phase-A n index
    const int h2   = wq & 1;                   // phase-B hm-half
    const int nh   = wq >> 1;                  // phase-B n-half

    const int cnt = (cta < LONGC) ? 8 : 7;
    const int p0  = (cta < LONGC) ? cta * 8 : LONGC * 8 + (cta - LONGC) * 7;

    unsigned long long acc[36];    // [j=0..11][k=0..2]: hm=12*h2+j, c=32k+lane
    unsigned long long Lacc[6];

    auto resetAcc = [&]() {
        #pragma unroll
        for (int i = 0; i < 36; i++) acc[i] = 0ull;
        #pragma unroll
        for (int i = 0; i < 6; i++) Lacc[i] = 0ull;
    };

    auto loadQ = [&](int bb) {
        for (int i = t; i < NHM * CHN; i += THREADS2) {
            const int hm = i / CHN, c = i % CHN;
            Qs[c * NHM + hm] = g_Qp[0][(size_t)bb * (NHM * CHN) + hm * CHN + c]
                             + g_Qp[1][(size_t)bb * (NHM * CHN) + hm * CHN + c];
        }
    };

    // flush current batch partials to slot (2*cta+seg). Caller guarantees a
    // barrier has passed since the last Phase-B read (Ps is dead -> staging).
    auto flush = [&](int bb, int seg) {
        float accf[36];
        #pragma unroll
        for (int a = 0; a < 36; a++) {
            float lo, hi;
            unpack2(acc[a], lo, hi);
            accf[a] = lo + hi;
        }
        if (nh == 1) {
            float* st = Ps0 + h2 * 1152;
            #pragma unroll
            for (int a = 0; a < 36; a++) st[a * 32 + lane] = accf[a];
        }
        __syncthreads();
        const int slot = 2 * cta + seg;
        const size_t outbase = (size_t)slot * (NHM * CHN);
        if (nh == 0) {
            const float* st = Ps0 + h2 * 1152;
            #pragma unroll
            for (int a = 0; a < 36; a++) {
                const float v = accf[a] + st[a * 32 + lane];
                const int j = a / 3, k = a % 3;
                g_accP[outbase + (12 * h2 + j) * CHN + 32 * k + lane] = v;
            }
        }
        // L reduction: warps 0,1 hold hm 0..11; warps 2,3 hold hm 12..23
        float Lv[12];
        #pragma unroll
        for (int jj = 0; jj < 6; jj++) unpack2(Lacc[jj], Lv[2 * jj], Lv[2 * jj + 1]);
        #pragma unroll
        for (int h = 0; h < 12; h++) {
            float v = Lv[h];
            #pragma unroll
            for (int m = 16; m >= 1; m >>= 1) v += __shfl_xor_sync(0xffffffffu, v, m);
            Lv[h] = v;
        }
        if (lane == 0) {
            #pragma unroll
            for (int h = 0; h < 12; h++) Lred[wq * 12 + h] = Lv[h];
        }
        __syncthreads();
        if (t < NHM) {
            const int gg = t / 12, rr = t % 12;
            g_LP[slot * NHM + t] =
                Lred[(2 * gg) * 12 + rr] + Lred[(2 * gg + 1) * 12 + rr];
        }
        if (t == 0) g_slotb[slot] = bb;
        __syncthreads();   // Lred/staging reuse + Qs rewrite ordering
    };

    // async tile loader for global pair p, half (0/1): 96x64 floats; 12/thread
    auto pf = [&](int buf, int p, int half) {
        const int bb = p / PAIRS_PER_B;
        const int pr = p % PAIRS_PER_B;
        const int base = pr * 128 + half * 64;
        const float* xb = x + (size_t)bb * CHN * HWN;
        uint32_t dst = (uint32_t)__cvta_generic_to_shared(Xs0 + buf * XS_FLOATS);
        #pragma unroll
        for (int k = 0; k < 12; k++) {
            const int idx = k * THREADS2 + t;
            const int c = idx >> 4, f4 = (idx & 15) << 2;
            cp_async16(dst + (uint32_t)(c * TNP + f4) * 4,
                       xb + (size_t)c * HWN + base + f4);
        }
        asm volatile("cp.async.commit_group;");
    };

    // phase B worker: one tile, this warp's (h2, nh) quadrant
    auto phaseB = [&](const float* Xs, const float* Ps) {
        #pragma unroll 2
        for (int q = 0; q < 8; q++) {
            const int n4 = 32 * nh + 4 * q;
            const ulonglong2 xx0 = *(const ulonglong2*)(Xs + (lane)      * TNP + n4);
            const ulonglong2 xx1 = *(const ulonglong2*)(Xs + (32 + lane) * TNP + n4);
            const ulonglong2 xx2 = *(const ulonglong2*)(Xs + (64 + lane) * TNP + n4);
            #pragma unroll
            for (int j = 0; j < 12; j++) {
                const int hm = 12 * h2 + j;
                const ulonglong2 pp = *(const ulonglong2*)(Ps + hm * TNP + n4);
                fma2(acc[j * 3 + 0], pp.x, xx0.x); fma2(acc[j * 3 + 0], pp.y, xx0.y);
                fma2(acc[j * 3 + 1], pp.x, xx1.x); fma2(acc[j * 3 + 1], pp.y, xx1.y);
                fma2(acc[j * 3 + 2], pp.x, xx2.x); fma2(acc[j * 3 + 2], pp.y, xx2.y);
            }
        }
    };

    int cur_b = p0 / PAIRS_PER_B;
    int seg = 0;
    loadQ(cur_b);
    resetAcc();
    pf(0, p0, 0);
    pf(1, p0, 1);

    for (int i = 0; i < cnt; i++) {
        const int p = p0 + i;
        const int bi = p / PAIRS_PER_B;
        if (bi != cur_b) {
            flush(cur_b, seg);     // safe: trailing bar of previous pair passed
            seg++;
            loadQ(bi);             // ordered before A by the wait+bar below
            resetAcc();
            cur_b = bi;
        }

        const float* XsA = Xs0;
        const float* XsB = Xs0 + XS_FLOATS;

        asm volatile("cp.async.wait_group 0;");   // both tiles of the pair
        __syncthreads();

        // ---- Phase A over both tiles: 12 hm per thread, n = ng ----
        {
            unsigned long long sA[6], sB[6];
            #pragma unroll
            for (int k = 0; k < 6; k++) { sA[k] = 0ull; sB[k] = 0ull; }
            const float* qbase = Qs + 12 * g;
            #pragma unroll 4
            for (int c = 0; c < CHN; c++) {
                const float xva = XsA[c * TNP + ng];
                const float xvb = XsB[c * TNP + ng];
                const unsigned long long xa = pack2(xva, xva);
                const unsigned long long xb2 = pack2(xvb, xvb);
                const ulonglong2* qr = (const ulonglong2*)(qbase + c * NHM);
                const ulonglong2 qa = qr[0];
                const ulonglong2 qb = qr[1];
                const ulonglong2 qc = qr[2];
                fma2(sA[0], qa.x, xa); fma2(sB[0], qa.x, xb2);
                fma2(sA[1], qa.y, xa); fma2(sB[1], qa.y, xb2);
                fma2(sA[2], qb.x, xa); fma2(sB[2], qb.x, xb2);
                fma2(sA[3], qb.y, xa); fma2(sB[3], qb.y, xb2);
                fma2(sA[4], qc.x, xa); fma2(sB[4], qc.x, xb2);
                fma2(sA[5], qc.y, xa); fma2(sB[5], qc.y, xb2);
            }
            #pragma unroll
            for (int jj = 0; jj < 6; jj++) {
                float a0, a1, b0, b1;
                unpack2(sA[jj], a0, a1);
                unpack2(sB[jj], b0, b1);
                const float pa0 = __expf(a0), pa1 = __expf(a1);
                const float pb0 = __expf(b0), pb1 = __expf(b1);
                Ps0[(12 * g + 2 * jj)     * TNP + ng] = pa0;
                Ps0[(12 * g + 2 * jj + 1) * TNP + ng] = pa1;
                Ps1[(12 * g + 2 * jj)     * TNP + ng] = pb0;
                Ps1[(12 * g + 2 * jj + 1) * TNP + ng] = pb1;
                add2(Lacc[jj], pack2(pa0, pa1));
                add2(Lacc[jj], pack2(pb0, pb1));
            }
        }
        __syncthreads();     // Ps visible; B reads ordered after A writes

        // ---- Phase B: both tiles, one barrier, then next pair's prefetch ----
        phaseB(XsA, Ps0);
        phaseB(XsB, Ps1);
        __syncthreads();     // all warps done reading buf0+buf1 (and Ps0/Ps1)
        if (i + 1 < cnt) {
            pf(0, p + 1, 0);
            pf(1, p + 1, 1);
        }
    }

    flush(cur_b, seg);
    if (t == 0 && seg == 0) g_slotb[2 * cta + 1] = -1;   // unused segment
}

// ---------------------------------------------------------------------------
// Kernel 3: combine tagged slot partials -> g_O[b][m][h*96+c] = acc / L
// ---------------------------------------------------------------------------
__global__ __launch_bounds__(256)
void combine_kernel() {
    const int i = blockIdx.x * 256 + threadIdx.x;   // 0 .. 147455
    const int b = i / (NHM * CHN);
    const int r = i % (NHM * CHN);
    const int hm = r / CHN, c = r % CHN;

    const int cta_lo = cta_of_pair(b * PAIRS_PER_B);
    const int cta_hi = cta_of_pair(b * PAIRS_PER_B + PAIRS_PER_B - 1);

    float a = 0.f, L = 0.f;
    for (int cc = cta_lo; cc <= cta_hi; cc++) {
        #pragma unroll
        for (int s = 0; s < 2; s++) {
            const int slot = 2 * cc + s;
            if (g_slotb[slot] == b) {
                a += g_accP[(size_t)slot * (NHM * CHN) + r];
                L += g_LP[slot * NHM + hm];
            }
        }
    }
    const int h = hm / 6, m = hm % 6;
    g_O[(size_t)b * 2304 + m * 384 + h * CHN + c] = a / L;
}

// ---------------------------------------------------------------------------
// Kernel 4: output projection + residual (d = t % 192; NOT a bitmask).
// ---------------------------------------------------------------------------
__global__ __launch_bounds__(384)
void proj_kernel(const float* __restrict__ z,
                 const float* __restrict__ Wo,
                 const float* __restrict__ bo,
                 float* __restrict__ out) {
    __shared__ float outRow[6 * 384];
    __shared__ float part[192 * 6];
    const int b = blockIdx.x;
    const int t = threadIdx.x;
    const int d = t % 192;

    for (int i = t; i < 2304; i += 384) outRow[i] = g_O[(size_t)b * 2304 + i];
    __syncthreads();

    const int j0 = (t >= 192) ? 192 : 0;
    float accm[6] = {0.f, 0.f, 0.f, 0.f, 0.f, 0.f};
    #pragma unroll 16
    for (int jj = 0; jj < 192; jj++) {
        const int j = j0 + jj;
        const float w = Wo[j * 192 + d];
        #pragma unroll
        for (int m = 0; m < 6; m++) accm[m] += outRow[m * 384 + j] * w;
    }
    if (t >= 192) {
        #pragma unroll
        for (int m = 0; m < 6; m++) part[d * 6 + m] = accm[m];
    }
    __syncthreads();
    if (t < 192) {
        const float bod = bo[d];
        #pragma unroll
        for (int m = 0; m < 6; m++)
            out[((size_t)b * 6 + m) * 192 + d] =
                z[((size_t)b * 6 + m) * 192 + d] + accm[m] + part[d * 6 + m] + bod;
    }
}

// ---------------------------------------------------------------------------
extern "C" void kernel_launch(void* const* d_in, const int* in_sizes, int n_in,
                              void* d_out, int out_size) {
    const float* x  = (const float*)d_in[0];
    const float* z  = (const float*)d_in[1];
    const float* Wq = (const float*)d_in[2];
    const float* bq = (const float*)d_in[3];
    const float* Wo = (const float*)d_in[4];
    const float* bo = (const float*)d_in[5];
    float* out = (float*)d_out;

    cudaFuncSetAttribute(attn_kernel,
                         cudaFuncAttributeMaxDynamicSharedMemorySize, SMEM2_BYTES);

    prof_marker<<<1, 32>>>();                                   // idx 0
    qproj_kernel<<<dim3(BATCH, 2), 384>>>(z, Wq, bq);           // idx 1
    prof_marker<<<1, 32>>>();                                   // idx 2
    attn_kernel<<<GRID2, THREADS2, SMEM2_BYTES>>>(x);           // idx 3 (ncu)
    combine_kernel<<<576, 256>>>();                             // idx 4
    proj_kernel<<<BATCH, 384>>>(z, Wo, bo, out);                // idx 5
}

// round 12
// speedup vs baseline: 1.7358x; 1.7358x over previous
#include <cuda_runtime.h>
#include <cuda_bf16.h>
#include <cstdint>

// ---------------------------------------------------------------------------
// Mobile2Former cross-attention, single-pass streaming softmax (scores bounded
// |s| < ~2; softmax shift-invariant so no max subtraction needed).
//
//   x : (64, 96, 112, 112) fp32 -> xf (b, n=12544, c=96), K = V = xf
//   q = SCALE * (z @ Wq + bq); p = exp(q.xf); out = (p@xf)/sum(p)
//   y = z + out @ Wo + bo
//
// Launch order: marker, qproj, marker, attn, combine, proj
//   (ncu captures absolute launch index 3 -> attn)
//
// attn (R12): tf32 mma.sync.m16n8k8 for BOTH GEMMs, on the proven R10/R4
// skeleton (cp.async wait-all double-buffered TN=64 tiles, grid (14,64)).
//   M=24 via two overlapping m16 tiles (rows 0-15, 8-23); dup rows discarded.
//   GEMM1 (scores): A = Q prepacked tf32 frags in smem; B from Xs. Warps
//     split n (16 each). C -> expf -> tf32 P to Ps + per-thread L.
//   GEMM2 (P @ X^T): warps split c (24 each -> full output rows per warp,
//     no cross-warp combine). A-frags from Ps, B from Xs, fp32 accum regs.
// ---------------------------------------------------------------------------

#define BATCH   64
#define CHN     96
#define HWN     12544
#define NHM     24
#define NSPLIT  14
#define CHUNK   896
#define TN      64
#define TNP     68             // padded row stride (floats); 272B, 16B-aligned
#define NTILES  14             // 64-wide tiles per split
#define THREADS2 128
#define XS_FLOATS (CHN * TNP)                 // 6528 per buffer
#define PS_FLOATS (NHM * TNP)                 // 1632
#define QF_U32    3072                        // 12 k x 2 mt x 32 lanes x 4
#define SMEM2_FLOATS (2*XS_FLOATS + PS_FLOATS + QF_U32 + 96)   // 17856
#define SMEM2_BYTES  (SMEM2_FLOATS * 4)       // 71424 B (3 CTAs/SM)
#define SCALE_F 0.10206207261596575f          // 96^-0.5

__device__ float g_Qp[2][BATCH * NHM * CHN];             // K-split q partials
__device__ float g_accP[BATCH * NSPLIT * NHM * CHN];     // split numerators
__device__ float g_LP[BATCH * NSPLIT * NHM];             // split denominators
__device__ float g_O[BATCH * 6 * 384];                   // attn out [b][m][h*96+c]

// ---- tf32 helpers ----
__device__ __forceinline__ uint32_t f2tf(float f) {
    uint32_t u;
    asm("cvt.rna.tf32.f32 %0, %1;" : "=r"(u) : "f"(f));
    return u;
}
__device__ __forceinline__ void mma8(float* c,
                                     uint32_t a0, uint32_t a1, uint32_t a2, uint32_t a3,
                                     uint32_t b0, uint32_t b1) {
    asm("mma.sync.aligned.m16n8k8.row.col.f32.tf32.tf32.f32 "
        "{%0,%1,%2,%3}, {%4,%5,%6,%7}, {%8,%9}, {%0,%1,%2,%3};"
        : "+f"(c[0]), "+f"(c[1]), "+f"(c[2]), "+f"(c[3])
        : "r"(a0), "r"(a1), "r"(a2), "r"(a3), "r"(b0), "r"(b1));
}
__device__ __forceinline__ void cp_async16(uint32_t dst, const float* src) {
    asm volatile("cp.async.cg.shared.global [%0], [%1], 16;" :: "r"(dst), "l"(src));
}

__global__ void prof_marker() {}

// ---------------------------------------------------------------------------
// Kernel 1: Q projection, grid (BATCH, 2): grid.y = K-half.
// ---------------------------------------------------------------------------
__global__ __launch_bounds__(384)
void qproj_kernel(const float* __restrict__ z,
                  const float* __restrict__ Wq,
                  const float* __restrict__ bq) {
    __shared__ float zs[6 * 192];
    const int b = blockIdx.x;
    const int half = blockIdx.y;
    const int j = threadIdx.x;
    for (int i = j; i < 6 * 192; i += 384) zs[i] = z[b * 6 * 192 + i];
    __syncthreads();

    const int d0 = 96 * half;
    float acc[6] = {0.f, 0.f, 0.f, 0.f, 0.f, 0.f};
    #pragma unroll 16
    for (int dd = 0; dd < 96; dd++) {
        const float w = Wq[(d0 + dd) * 384 + j];
        #pragma unroll
        for (int m = 0; m < 6; m++) acc[m] += zs[m * 192 + d0 + dd] * w;
    }
    const int h = j / CHN, c = j % CHN;
    const float bias = (half == 0) ? bq[j] : 0.f;
    #pragma unroll
    for (int m = 0; m < 6; m++)
        g_Qp[half][(size_t)b * (NHM * CHN) + (h * 6 + m) * CHN + c] =
            (acc[m] + bias) * SCALE_F;
}

// ---------------------------------------------------------------------------
// Kernel 2: streaming attention, tf32 tensor-core GEMMs.
// ---------------------------------------------------------------------------
__global__ __launch_bounds__(THREADS2, 3)
void attn_kernel(const float* __restrict__ x) {
    extern __shared__ float sm[];
    float*    Xs0   = sm;                            // [2][96][68]
    float*    Ps    = sm + 2 * XS_FLOATS;            // [24][68] (tf32-valued)
    uint32_t* qfrag = (uint32_t*)(sm + 2 * XS_FLOATS + PS_FLOATS);  // [12][2][32][4]
    float*    Lred  = sm + 2 * XS_FLOATS + PS_FLOATS + QF_U32;      // [4][24]

    const int t     = threadIdx.x;
    const int b     = blockIdx.y;
    const int split = blockIdx.x;
    const int lane  = t & 31;
    const int w     = t >> 5;
    const int gid   = lane >> 2;     // 0..7
    const int tig   = lane & 3;      // 0..3

    // ---- stage Q (coalesced) into Xs0, then build tf32 A-fragments ----
    {
        const size_t qb = (size_t)b * (NHM * CHN);
        for (int i = t; i < NHM * CHN; i += THREADS2)
            Xs0[i] = g_Qp[0][qb + i] + g_Qp[1][qb + i];
        __syncthreads();
        // 24 frag-sets (12 ksteps x 2 mtiles); mtile m covers rows m*8..m*8+15
        #pragma unroll
        for (int pass = 0; pass < 6; pass++) {
            const int set = pass * 4 + w;
            const int k = set >> 1, mt = set & 1;
            const int r0 = mt * 8 + gid;
            const int c0 = k * 8 + tig;
            uint4 u;
            u.x = f2tf(Xs0[r0 * 96 + c0]);
            u.y = f2tf(Xs0[(r0 + 8) * 96 + c0]);
            u.z = f2tf(Xs0[r0 * 96 + c0 + 4]);
            u.w = f2tf(Xs0[(r0 + 8) * 96 + c0 + 4]);
            ((uint4*)qfrag)[(k * 2 + mt) * 32 + lane] = u;
        }
        __syncthreads();
    }

    float Oacc[2][3][4];         // [mtile][c-tile][frag]: GEMM2 accumulators
    float Lp[3] = {0.f, 0.f, 0.f};  // exp sums: hm = gid, 8+gid, 16+gid
    #pragma unroll
    for (int a = 0; a < 2; a++)
        #pragma unroll
        for (int ct = 0; ct < 3; ct++)
            #pragma unroll
            for (int i = 0; i < 4; i++) Oacc[a][ct][i] = 0.f;

    const float* xb = x + (size_t)b * CHN * HWN;
    const int n0 = split * CHUNK;
    const int n0w = 16 * w;      // GEMM1: warp's n-quarter
    const int c0w = 24 * w;      // GEMM2: warp's c-quarter

    // async tile loader: 96x64 floats = 1536 float4; 12 per thread
    auto prefetch = [&](int buf, int tile) {
        const int base = n0 + tile * TN;
        uint32_t dst = (uint32_t)__cvta_generic_to_shared(Xs0 + buf * XS_FLOATS);
        #pragma unroll
        for (int kk = 0; kk < 12; kk++) {
            const int idx = kk * THREADS2 + t;
            const int c = idx >> 4, f4 = (idx & 15) << 2;
            cp_async16(dst + (uint32_t)(c * TNP + f4) * 4,
                       xb + (size_t)c * HWN + base + f4);
        }
        asm volatile("cp.async.commit_group;");
    };

    prefetch(0, 0);

    for (int tile = 0; tile < NTILES; tile++) {
        const int buf = tile & 1;
        const float* Xs = Xs0 + buf * XS_FLOATS;

        asm volatile("cp.async.wait_group 0;");
        __syncthreads();                          // tile data visible
        if (tile + 1 < NTILES) prefetch(buf ^ 1, tile + 1);  // other buf free

        // ---- GEMM1: scores S[24 x 16] for this warp's n-quarter ----
        float c4[2][2][4];
        #pragma unroll
        for (int a = 0; a < 2; a++)
            #pragma unroll
            for (int nt = 0; nt < 2; nt++)
                #pragma unroll
                for (int i = 0; i < 4; i++) c4[a][nt][i] = 0.f;

        #pragma unroll
        for (int k = 0; k < 12; k++) {
            const uint4 af0 = ((const uint4*)qfrag)[(k * 2 + 0) * 32 + lane];
            const uint4 af1 = ((const uint4*)qfrag)[(k * 2 + 1) * 32 + lane];
            #pragma unroll
            for (int nt = 0; nt < 2; nt++) {
                const int ncol = n0w + nt * 8 + gid;
                const uint32_t b0 = f2tf(Xs[(k * 8 + tig) * TNP + ncol]);
                const uint32_t b1 = f2tf(Xs[(k * 8 + tig + 4) * TNP + ncol]);
                mma8(c4[0][nt], af0.x, af0.y, af0.z, af0.w, b0, b1);
                mma8(c4[1][nt], af1.x, af1.y, af1.z, af1.w, b0, b1);
            }
        }

        // ---- exp -> Ps (tf32-rounded) + L. mtile1 rows 8-15 are dups: skip.
        #pragma unroll
        for (int nt = 0; nt < 2; nt++) {
            const int col = n0w + nt * 8 + 2 * tig;
            // mtile0, rows gid (c0,c1) and gid+8 (c2,c3)
            {
                const float p0 = __uint_as_float(f2tf(__expf(c4[0][nt][0])));
                const float p1 = __uint_as_float(f2tf(__expf(c4[0][nt][1])));
                Ps[gid * TNP + col]     = p0;
                Ps[gid * TNP + col + 1] = p1;
                Lp[0] += p0 + p1;
            }
            {
                const float p0 = __uint_as_float(f2tf(__expf(c4[0][nt][2])));
                const float p1 = __uint_as_float(f2tf(__expf(c4[0][nt][3])));
                Ps[(8 + gid) * TNP + col]     = p0;
                Ps[(8 + gid) * TNP + col + 1] = p1;
                Lp[1] += p0 + p1;
            }
            // mtile1, rows 16+gid (c2,c3 only)
            {
                const float p0 = __uint_as_float(f2tf(__expf(c4[1][nt][2])));
                const float p1 = __uint_as_float(f2tf(__expf(c4[1][nt][3])));
                Ps[(16 + gid) * TNP + col]     = p0;
                Ps[(16 + gid) * TNP + col + 1] = p1;
                Lp[2] += p0 + p1;
            }
        }
        __syncthreads();     // all of Ps visible to all warps

        // ---- GEMM2: Oacc += P[24 x 64] @ X^T[64 x 24] (warp's c-quarter) ----
        #pragma unroll
        for (int k = 0; k < 8; k++) {
            const int nc = k * 8 + tig;
            const uint32_t pa0 = __float_as_uint(Ps[gid * TNP + nc]);
            const uint32_t pa1 = __float_as_uint(Ps[(8 + gid) * TNP + nc]);
            const uint32_t pa2 = __float_as_uint(Ps[gid * TNP + nc + 4]);
            const uint32_t pa3 = __float_as_uint(Ps[(8 + gid) * TNP + nc + 4]);
            const uint32_t pb1 = __float_as_uint(Ps[(16 + gid) * TNP + nc]);
            const uint32_t pb3 = __float_as_uint(Ps[(16 + gid) * TNP + nc + 4]);
            #pragma unroll
            for (int ct = 0; ct < 3; ct++) {
                const int crow = c0w + ct * 8 + gid;
                const uint32_t b0 = f2tf(Xs[crow * TNP + nc]);
                const uint32_t b1 = f2tf(Xs[crow * TNP + nc + 4]);
                mma8(Oacc[0][ct], pa0, pa1, pa2, pa3, b0, b1);   // rows 0-15
                mma8(Oacc[1][ct], pa1, pb1, pa3, pb3, b0, b1);   // rows 8-23
            }
        }
        __syncthreads();     // close Xs/Ps reads before refill/rewrite
    }

    // ---- epilogue: each warp owns hm 0..23 x its 24 c columns ----
    const size_t outbase = (size_t)(b * NSPLIT + split) * (NHM * CHN);
    #pragma unroll
    for (int ct = 0; ct < 3; ct++) {
        const int col = c0w + ct * 8 + 2 * tig;
        g_accP[outbase + gid * CHN + col]            = Oacc[0][ct][0];
        g_accP[outbase + gid * CHN + col + 1]        = Oacc[0][ct][1];
        g_accP[outbase + (8 + gid) * CHN + col]      = Oacc[0][ct][2];
        g_accP[outbase + (8 + gid) * CHN + col + 1]  = Oacc[0][ct][3];
        g_accP[outbase + (16 + gid) * CHN + col]     = Oacc[1][ct][2];   // rows 16-23
        g_accP[outbase + (16 + gid) * CHN + col + 1] = Oacc[1][ct][3];
    }

    // ---- L reduction: sum over tig lanes, then over the 4 warps ----
    #pragma unroll
    for (int i = 0; i < 3; i++) {
        float v = Lp[i];
        v += __shfl_xor_sync(0xffffffffu, v, 1);
        v += __shfl_xor_sync(0xffffffffu, v, 2);
        Lp[i] = v;
    }
    if (tig == 0) {
        Lred[w * 24 + gid]      = Lp[0];
        Lred[w * 24 + 8 + gid]  = Lp[1];
        Lred[w * 24 + 16 + gid] = Lp[2];
    }
    __syncthreads();
    if (t < NHM) {
        g_LP[(b * NSPLIT + split) * NHM + t] =
            Lred[t] + Lred[24 + t] + Lred[48 + t] + Lred[72 + t];
    }
}

// ---------------------------------------------------------------------------
// Kernel 3: combine split partials -> g_O[b][m][h*96+c] = (sum_s acc)/(sum_s L)
// ---------------------------------------------------------------------------
__global__ __launch_bounds__(256)
void combine_kernel() {
    const int i = blockIdx.x * 256 + threadIdx.x;   // 0 .. 147455
    const int b = i / (NHM * CHN);
    const int r = i % (NHM * CHN);
    const int hm = r / CHN, c = r % CHN;
    float a = 0.f, L = 0.f;
    #pragma unroll
    for (int s = 0; s < NSPLIT; s++) {
        a += g_accP[(size_t)(b * NSPLIT + s) * (NHM * CHN) + r];
        L += g_LP[(b * NSPLIT + s) * NHM + hm];
    }
    const int h = hm / 6, m = hm % 6;
    g_O[(size_t)b * 2304 + m * 384 + h * CHN + c] = a / L;
}

// ---------------------------------------------------------------------------
// Kernel 4: output projection + residual (d = t % 192; NOT a bitmask).
// ---------------------------------------------------------------------------
__global__ __launch_bounds__(384)
void proj_kernel(const float* __restrict__ z,
                 const float* __restrict__ Wo,
                 const float* __restrict__ bo,
                 float* __restrict__ out) {
    __shared__ float outRow[6 * 384];
    __shared__ float part[192 * 6];
    const int b = blockIdx.x;
    const int t = threadIdx.x;
    const int d = t % 192;

    for (int i = t; i < 2304; i += 384) outRow[i] = g_O[(size_t)b * 2304 + i];
    __syncthreads();

    const int j0 = (t >= 192) ? 192 : 0;
    float accm[6] = {0.f, 0.f, 0.f, 0.f, 0.f, 0.f};
    #pragma unroll 16
    for (int jj = 0; jj < 192; jj++) {
        const int j = j0 + jj;
        const float w = Wo[j * 192 + d];
        #pragma unroll
        for (int m = 0; m < 6; m++) accm[m] += outRow[m * 384 + j] * w;
    }
    if (t >= 192) {
        #pragma unroll
        for (int m = 0; m < 6; m++) part[d * 6 + m] = accm[m];
    }
    __syncthreads();
    if (t < 192) {
        const float bod = bo[d];
        #pragma unroll
        for (int m = 0; m < 6; m++)
            out[((size_t)b * 6 + m) * 192 + d] =
                z[((size_t)b * 6 + m) * 192 + d] + accm[m] + part[d * 6 + m] + bod;
    }
}

// ---------------------------------------------------------------------------
extern "C" void kernel_launch(void* const* d_in, const int* in_sizes, int n_in,
                              void* d_out, int out_size) {
    const float* x  = (const float*)d_in[0];
    const float* z  = (const float*)d_in[1];
    const float* Wq = (const float*)d_in[2];
    const float* bq = (const float*)d_in[3];
    const float* Wo = (const float*)d_in[4];
    const float* bo = (const float*)d_in[5];
    float* out = (float*)d_out;

    cudaFuncSetAttribute(attn_kernel,
                         cudaFuncAttributeMaxDynamicSharedMemorySize, SMEM2_BYTES);

    prof_marker<<<1, 32>>>();                                   // idx 0
    qproj_kernel<<<dim3(BATCH, 2), 384>>>(z, Wq, bq);           // idx 1
    prof_marker<<<1, 32>>>();                                   // idx 2
    attn_kernel<<<dim3(NSPLIT, BATCH), THREADS2, SMEM2_BYTES>>>(x);  // idx 3 (ncu)
    combine_kernel<<<576, 256>>>();                             // idx 4
    proj_kernel<<<BATCH, 384>>>(z, Wo, bo, out);                // idx 5
}

// round 13
// speedup vs baseline: 1.8476x; 1.0644x over previous
#include <cuda_runtime.h>
#include <cuda_bf16.h>
#include <cstdint>

// ---------------------------------------------------------------------------
// Mobile2Former cross-attention, single-pass streaming softmax (scores bounded
// |s| < ~2; softmax shift-invariant so no max subtraction needed).
//
//   x : (64, 96, 112, 112) fp32 -> xf (b, n=12544, c=96), K = V = xf
//   q = SCALE * (z @ Wq + bq); p = exp(q.xf); out = (p@xf)/sum(p)
//   y = z + out @ Wo + bo
//
// Launch order: marker, qproj, marker, attn, combine, proj
//   (ncu captures absolute launch index 3 -> attn)
//
// attn (R13 = R12 + pair processing + qfrag dedup):
//   tf32 mma.sync.m16n8k8 both GEMMs; TN=64 tiles processed in PAIRS on the
//   proven R8 skeleton. Q fragments (tile-invariant) are loaded from smem once
//   per k per PAIR and applied to both tiles -> qfrag crossbar traffic halved.
//   qfrag dedup: mtiles share rows 8-15 -> 6 unique u32/lane/k (uint4+uint2).
//   Pipeline: wait-all; bar; GEMM1(pair)+exp; bar; GEMM2(A); bar; pf(bufA);
//             GEMM2(B); bar; pf(bufB).
// ---------------------------------------------------------------------------

#define BATCH   64
#define CHN     96
#define HWN     12544
#define NSPLIT  14
#define CHUNK   896
#define NHM     24
#define TN      64
#define TNP     68             // padded row stride (floats)
#define NTILES  14
#define NPAIRS  7
#define THREADS2 128
#define XS_FLOATS (CHN * TNP)                 // 6528 per buffer
#define PS_FLOATS (NHM * TNP)                 // 1632 per tile
#define QA_U32   (12 * 32 * 4)                // 1536
#define QB_U32   (12 * 32 * 2)                // 768
#define SMEM2_FLOATS (2*XS_FLOATS + 2*PS_FLOATS + QA_U32 + QB_U32 + 96)  // 18720
#define SMEM2_BYTES  (SMEM2_FLOATS * 4)       // 74880 B (3 CTAs/SM)
#define SCALE_F 0.10206207261596575f          // 96^-0.5
#define QSPLIT  4

__device__ float g_Qp[QSPLIT][BATCH * NHM * CHN];        // K-split q partials
__device__ float g_accP[BATCH * NSPLIT * NHM * CHN];     // split numerators
__device__ float g_LP[BATCH * NSPLIT * NHM];             // split denominators
__device__ float g_O[BATCH * 6 * 384];                   // attn out [b][m][h*96+c]

// ---- tf32 helpers ----
__device__ __forceinline__ uint32_t f2tf(float f) {
    uint32_t u;
    asm("cvt.rna.tf32.f32 %0, %1;" : "=r"(u) : "f"(f));
    return u;
}
__device__ __forceinline__ void mma8(float* c,
                                     uint32_t a0, uint32_t a1, uint32_t a2, uint32_t a3,
                                     uint32_t b0, uint32_t b1) {
    asm("mma.sync.aligned.m16n8k8.row.col.f32.tf32.tf32.f32 "
        "{%0,%1,%2,%3}, {%4,%5,%6,%7}, {%8,%9}, {%0,%1,%2,%3};"
        : "+f"(c[0]), "+f"(c[1]), "+f"(c[2]), "+f"(c[3])
        : "r"(a0), "r"(a1), "r"(a2), "r"(a3), "r"(b0), "r"(b1));
}
__device__ __forceinline__ void cp_async16(uint32_t dst, const float* src) {
    asm volatile("cp.async.cg.shared.global [%0], [%1], 16;" :: "r"(dst), "l"(src));
}

__global__ void prof_marker() {}

// ---------------------------------------------------------------------------
// Kernel 1: Q projection, grid (BATCH, 4): grid.y = K-quarter (48 d each).
// ---------------------------------------------------------------------------
__global__ __launch_bounds__(384)
void qproj_kernel(const float* __restrict__ z,
                  const float* __restrict__ Wq,
                  const float* __restrict__ bq) {
    __shared__ float zs[6 * 192];
    const int b = blockIdx.x;
    const int part = blockIdx.y;
    const int j = threadIdx.x;
    for (int i = j; i < 6 * 192; i += 384) zs[i] = z[b * 6 * 192 + i];
    __syncthreads();

    const int d0 = 48 * part;
    float acc[6] = {0.f, 0.f, 0.f, 0.f, 0.f, 0.f};
    #pragma unroll 16
    for (int dd = 0; dd < 48; dd++) {
        const float w = Wq[(d0 + dd) * 384 + j];
        #pragma unroll
        for (int m = 0; m < 6; m++) acc[m] += zs[m * 192 + d0 + dd] * w;
    }
    const int h = j / CHN, c = j % CHN;
    const float bias = (part == 0) ? bq[j] : 0.f;
    #pragma unroll
    for (int m = 0; m < 6; m++)
        g_Qp[part][(size_t)b * (NHM * CHN) + (h * 6 + m) * CHN + c] =
            (acc[m] + bias) * SCALE_F;
}

// ---------------------------------------------------------------------------
// Kernel 2: streaming attention, tf32 tensor cores, pair-processed tiles.
// ---------------------------------------------------------------------------
__global__ __launch_bounds__(THREADS2, 3)
void attn_kernel(const float* __restrict__ x) {
    extern __shared__ float sm[];
    float*    Xs0  = sm;                                   // [2][96][68]
    float*    PsA  = sm + 2 * XS_FLOATS;                   // [24][68]
    float*    PsB  = PsA + PS_FLOATS;                      // [24][68]
    uint4*    qA   = (uint4*)(PsB + PS_FLOATS);            // [12][32]
    uint2*    qB   = (uint2*)((uint32_t*)qA + QA_U32);     // [12][32]
    float*    Lred = (float*)((uint32_t*)qA + QA_U32 + QB_U32);  // [4][24]

    const int t     = threadIdx.x;
    const int b     = blockIdx.y;
    const int split = blockIdx.x;
    const int lane  = t & 31;
    const int w     = t >> 5;
    const int gid   = lane >> 2;     // 0..7
    const int tig   = lane & 3;      // 0..3

    // ---- stage Q (coalesced) into Xs0, then build deduped tf32 fragments ----
    {
        const size_t qb0 = (size_t)b * (NHM * CHN);
        for (int i = t; i < NHM * CHN; i += THREADS2)
            Xs0[i] = g_Qp[0][qb0 + i] + g_Qp[1][qb0 + i]
                   + g_Qp[2][qb0 + i] + g_Qp[3][qb0 + i];
        __syncthreads();
        // rows gid, 8+gid, 16+gid x cols (k*8+tig, +4): 6 unique u32/lane/k
        #pragma unroll
        for (int i = 0; i < 3; i++) {
            const int k = w * 3 + i;
            const int c0 = k * 8 + tig;
            const uint32_t q0 = f2tf(Xs0[gid * 96 + c0]);
            const uint32_t q1 = f2tf(Xs0[(8 + gid) * 96 + c0]);
            const uint32_t q2 = f2tf(Xs0[(16 + gid) * 96 + c0]);
            const uint32_t q3 = f2tf(Xs0[gid * 96 + c0 + 4]);
            const uint32_t q4 = f2tf(Xs0[(8 + gid) * 96 + c0 + 4]);
            const uint32_t q5 = f2tf(Xs0[(16 + gid) * 96 + c0 + 4]);
            qA[k * 32 + lane] = make_uint4(q0, q1, q3, q4);
            qB[k * 32 + lane] = make_uint2(q2, q5);
        }
        __syncthreads();
    }

    float Oacc[2][3][4];            // [mtile][c-tile][frag]
    float Lp[3] = {0.f, 0.f, 0.f};  // exp sums: hm = gid, 8+gid, 16+gid
    #pragma unroll
    for (int a = 0; a < 2; a++)
        #pragma unroll
        for (int ct = 0; ct < 3; ct++)
            #pragma unroll
            for (int i = 0; i < 4; i++) Oacc[a][ct][i] = 0.f;

    const float* xb = x + (size_t)b * CHN * HWN;
    const int n0 = split * CHUNK;
    const int n0w = 16 * w;      // GEMM1: warp's n-quarter
    const int c0w = 24 * w;      // GEMM2: warp's c-quarter

    auto prefetch = [&](int buf, int tile) {
        const int base = n0 + tile * TN;
        uint32_t dst = (uint32_t)__cvta_generic_to_shared(Xs0 + buf * XS_FLOATS);
        #pragma unroll
        for (int kk = 0; kk < 12; kk++) {
            const int idx = kk * THREADS2 + t;
            const int c = idx >> 4, f4 = (idx & 15) << 2;
            cp_async16(dst + (uint32_t)(c * TNP + f4) * 4,
                       xb + (size_t)c * HWN + base + f4);
        }
        asm volatile("cp.async.commit_group;");
    };

    // exp + store + L for one tile's score frags
    auto expStore = [&](float c4[2][2][4], float* Ps) {
        #pragma unroll
        for (int nt = 0; nt < 2; nt++) {
            const int col = n0w + nt * 8 + 2 * tig;
            {
                const float p0 = __uint_as_float(f2tf(__expf(c4[0][nt][0])));
                const float p1 = __uint_as_float(f2tf(__expf(c4[0][nt][1])));
                Ps[gid * TNP + col] = p0; Ps[gid * TNP + col + 1] = p1;
                Lp[0] += p0 + p1;
            }
            {
                const float p0 = __uint_as_float(f2tf(__expf(c4[0][nt][2])));
                const float p1 = __uint_as_float(f2tf(__expf(c4[0][nt][3])));
                Ps[(8 + gid) * TNP + col] = p0; Ps[(8 + gid) * TNP + col + 1] = p1;
                Lp[1] += p0 + p1;
            }
            {
                const float p0 = __uint_as_float(f2tf(__expf(c4[1][nt][2])));
                const float p1 = __uint_as_float(f2tf(__expf(c4[1][nt][3])));
                Ps[(16 + gid) * TNP + col] = p0; Ps[(16 + gid) * TNP + col + 1] = p1;
                Lp[2] += p0 + p1;
            }
        }
    };

    // GEMM2 for one tile: Oacc += P[24 x 64] @ X^T (warp's c-quarter)
    auto gemm2 = [&](const float* Xs, const float* Ps) {
        #pragma unroll
        for (int k = 0; k < 8; k++) {
            const int nc = k * 8 + tig;
            const uint32_t pa0 = __float_as_uint(Ps[gid * TNP + nc]);
            const uint32_t pa1 = __float_as_uint(Ps[(8 + gid) * TNP + nc]);
            const uint32_t pa2 = __float_as_uint(Ps[gid * TNP + nc + 4]);
            const uint32_t pa3 = __float_as_uint(Ps[(8 + gid) * TNP + nc + 4]);
            const uint32_t pb1 = __float_as_uint(Ps[(16 + gid) * TNP + nc]);
            const uint32_t pb3 = __float_as_uint(Ps[(16 + gid) * TNP + nc + 4]);
            #pragma unroll
            for (int ct = 0; ct < 3; ct++) {
                const int crow = c0w + ct * 8 + gid;
                const uint32_t b0 = f2tf(Xs[crow * TNP + nc]);
                const uint32_t b1 = f2tf(Xs[crow * TNP + nc + 4]);
                mma8(Oacc[0][ct], pa0, pa1, pa2, pa3, b0, b1);   // rows 0-15
                mma8(Oacc[1][ct], pa1, pb1, pa3, pb3, b0, b1);   // rows 8-23
            }
        }
    };

    prefetch(0, 0);
    prefetch(1, 1);

    for (int r = 0; r < NPAIRS; r++) {
        const float* XsA = Xs0;
        const float* XsB = Xs0 + XS_FLOATS;

        asm volatile("cp.async.wait_group 0;");   // both tiles of the pair
        __syncthreads();

        // ---- GEMM1 over both tiles: Q frags loaded once per k ----
        float cA[2][2][4], cB[2][2][4];
        #pragma unroll
        for (int a = 0; a < 2; a++)
            #pragma unroll
            for (int nt = 0; nt < 2; nt++)
                #pragma unroll
                for (int i = 0; i < 4; i++) { cA[a][nt][i] = 0.f; cB[a][nt][i] = 0.f; }

        #pragma unroll
        for (int k = 0; k < 12; k++) {
            const uint4 fa = qA[k * 32 + lane];
            const uint2 fb = qB[k * 32 + lane];
            // af0 = {fa.x, fa.y, fa.z, fa.w}; af1 = {fa.y, fb.x, fa.w, fb.y}
            #pragma unroll
            for (int nt = 0; nt < 2; nt++) {
                const int ncol = n0w + nt * 8 + gid;
                const int r0 = (k * 8 + tig) * TNP + ncol;
                const int r1 = (k * 8 + tig + 4) * TNP + ncol;
                {
                    const uint32_t b0 = f2tf(XsA[r0]);
                    const uint32_t b1 = f2tf(XsA[r1]);
                    mma8(cA[0][nt], fa.x, fa.y, fa.z, fa.w, b0, b1);
                    mma8(cA[1][nt], fa.y, fb.x, fa.w, fb.y, b0, b1);
                }
                {
                    const uint32_t b0 = f2tf(XsB[r0]);
                    const uint32_t b1 = f2tf(XsB[r1]);
                    mma8(cB[0][nt], fa.x, fa.y, fa.z, fa.w, b0, b1);
                    mma8(cB[1][nt], fa.y, fb.x, fa.w, fb.y, b0, b1);
                }
            }
        }

        expStore(cA, PsA);
        expStore(cB, PsB);
        __syncthreads();     // Ps visible to all warps

        // ---- GEMM2 tile A; free bufA; refill ----
        gemm2(XsA, PsA);
        __syncthreads();     // all warps done reading bufA
        if (r + 1 < NPAIRS) prefetch(0, 2 * r + 2);

        // ---- GEMM2 tile B; free bufB; refill ----
        gemm2(XsB, PsB);
        __syncthreads();     // all warps done reading bufB (and PsA/PsB)
        if (r + 1 < NPAIRS) prefetch(1, 2 * r + 3);
    }

    // ---- epilogue: each warp owns hm 0..23 x its 24 c columns ----
    const size_t outbase = (size_t)(b * NSPLIT + split) * (NHM * CHN);
    #pragma unroll
    for (int ct = 0; ct < 3; ct++) {
        const int col = c0w + ct * 8 + 2 * tig;
        g_accP[outbase + gid * CHN + col]            = Oacc[0][ct][0];
        g_accP[outbase + gid * CHN + col + 1]        = Oacc[0][ct][1];
        g_accP[outbase + (8 + gid) * CHN + col]      = Oacc[0][ct][2];
        g_accP[outbase + (8 + gid) * CHN + col + 1]  = Oacc[0][ct][3];
        g_accP[outbase + (16 + gid) * CHN + col]     = Oacc[1][ct][2];
        g_accP[outbase + (16 + gid) * CHN + col + 1] = Oacc[1][ct][3];
    }

    // ---- L reduction: sum over tig lanes, then over the 4 warps ----
    #pragma unroll
    for (int i = 0; i < 3; i++) {
        float v = Lp[i];
        v += __shfl_xor_sync(0xffffffffu, v, 1);
        v += __shfl_xor_sync(0xffffffffu, v, 2);
        Lp[i] = v;
    }
    if (tig == 0) {
        Lred[w * 24 + gid]      = Lp[0];
        Lred[w * 24 + 8 + gid]  = Lp[1];
        Lred[w * 24 + 16 + gid] = Lp[2];
    }
    __syncthreads();
    if (t < NHM) {
        g_LP[(b * NSPLIT + split) * NHM + t] =
            Lred[t] + Lred[24 + t] + Lred[48 + t] + Lred[72 + t];
    }
}

// ---------------------------------------------------------------------------
// Kernel 3: combine split partials -> g_O[b][m][h*96+c] = (sum_s acc)/(sum_s L)
// ---------------------------------------------------------------------------
__global__ __launch_bounds__(256)
void combine_kernel() {
    const int i = blockIdx.x * 256 + threadIdx.x;   // 0 .. 147455
    const int b = i / (NHM * CHN);
    const int r = i % (NHM * CHN);
    const int hm = r / CHN, c = r % CHN;
    float a = 0.f, L = 0.f;
    #pragma unroll
    for (int s = 0; s < NSPLIT; s++) {
        a += g_accP[(size_t)(b * NSPLIT + s) * (NHM * CHN) + r];
        L += g_LP[(b * NSPLIT + s) * NHM + hm];
    }
    const int h = hm / 6, m = hm % 6;
    g_O[(size_t)b * 2304 + m * 384 + h * CHN + c] = a / L;
}

// ---------------------------------------------------------------------------
// Kernel 4: output projection + residual (d = t % 192; NOT a bitmask).
// ---------------------------------------------------------------------------
__global__ __launch_bounds__(384)
void proj_kernel(const float* __restrict__ z,
                 const float* __restrict__ Wo,
                 const float* __restrict__ bo,
                 float* __restrict__ out) {
    __shared__ float outRow[6 * 384];
    __shared__ float part[192 * 6];
    const int b = blockIdx.x;
    const int t = threadIdx.x;
    const int d = t % 192;

    for (int i = t; i < 2304; i += 384) outRow[i] = g_O[(size_t)b * 2304 + i];
    __syncthreads();

    const int j0 = (t >= 192) ? 192 : 0;
    float accm[6] = {0.f, 0.f, 0.f, 0.f, 0.f, 0.f};
    #pragma unroll 16
    for (int jj = 0; jj < 192; jj++) {
        const int j = j0 + jj;
        const float w = Wo[j * 192 + d];
        #pragma unroll
        for (int m = 0; m < 6; m++) accm[m] += outRow[m * 384 + j] * w;
    }
    if (t >= 192) {
        #pragma unroll
        for (int m = 0; m < 6; m++) part[d * 6 + m] = accm[m];
    }
    __syncthreads();
    if (t < 192) {
        const float bod = bo[d];
        #pragma unroll
        for (int m = 0; m < 6; m++)
            out[((size_t)b * 6 + m) * 192 + d] =
                z[((size_t)b * 6 + m) * 192 + d] + accm[m] + part[d * 6 + m] + bod;
    }
}

// ---------------------------------------------------------------------------
extern "C" void kernel_launch(void* const* d_in, const int* in_sizes, int n_in,
                              void* d_out, int out_size) {
    const float* x  = (const float*)d_in[0];
    const float* z  = (const float*)d_in[1];
    const float* Wq = (const float*)d_in[2];
    const float* bq = (const float*)d_in[3];
    const float* Wo = (const float*)d_in[4];
    const float* bo = (const float*)d_in[5];
    float* out = (float*)d_out;

    cudaFuncSetAttribute(attn_kernel,
                         cudaFuncAttributeMaxDynamicSharedMemorySize, SMEM2_BYTES);

    prof_marker<<<1, 32>>>();                                   // idx 0
    qproj_kernel<<<dim3(BATCH, QSPLIT), 384>>>(z, Wq, bq);      // idx 1
    prof_marker<<<1, 32>>>();                                   // idx 2
    attn_kernel<<<dim3(NSPLIT, BATCH), THREADS2, SMEM2_BYTES>>>(x);  // idx 3 (ncu)
    combine_kernel<<<576, 256>>>();                             // idx 4
    proj_kernel<<<BATCH, 384>>>(z, Wo, bo, out);                // idx 5
}